// round 5
// baseline (speedup 1.0000x reference)
#include <cuda_runtime.h>

#define NBv   8
#define ND    512
#define NCHv  3
#define NMIXv 4
#define HD    128
#define NTILE 16          // 512 / 32 a-tiles

typedef unsigned long long u64;

// ---------------- device scratch ----------------
__device__ float g_part[NBv * NCHv * NTILE * HD];  // per-(b,k,tile) layer1 partials
__device__ int   g_cnt[NBv];                        // arrival counters (zero-init)

// ---------------- f32x2 helpers (sm_100a packed math) ----------------
__device__ __forceinline__ u64 fma2(u64 a, u64 b, u64 c) {
    u64 d; asm("fma.rn.f32x2 %0,%1,%2,%3;" : "=l"(d) : "l"(a), "l"(b), "l"(c)); return d;
}
__device__ __forceinline__ u64 add2(u64 a, u64 b) {
    u64 d; asm("add.rn.f32x2 %0,%1,%2;" : "=l"(d) : "l"(a), "l"(b)); return d;
}
__device__ __forceinline__ u64 mul2(u64 a, u64 b) {
    u64 d; asm("mul.rn.f32x2 %0,%1,%2;" : "=l"(d) : "l"(a), "l"(b)); return d;
}
__device__ __forceinline__ u64 pack2(float lo, float hi) {
    u64 d; asm("mov.b64 %0,{%1,%2};" : "=l"(d) : "f"(lo), "f"(hi)); return d;
}
__device__ __forceinline__ void unpack2(float& lo, float& hi, u64 v) {
    asm("mov.b64 {%0,%1},%2;" : "=f"(lo), "=f"(hi) : "l"(v));
}
__device__ __forceinline__ float ex2f(float x) {
    float r; asm("ex2.approx.f32 %0, %1;" : "=f"(r) : "f"(x)); return r;
}
__device__ __forceinline__ void lds2(u64& lo, u64& hi, const float4* p) {
    unsigned a = (unsigned)__cvta_generic_to_shared(p);
    asm volatile("ld.shared.v2.b64 {%0,%1}, [%2];" : "=l"(lo), "=l"(hi) : "r"(a));
}

// ---------------- shared-memory overlays ----------------
struct Tables {                       // live during pair loop only
    float4 A[ND];   // {u0m0,u0m1,u1m0,u1m1}
    float4 B[ND];   // {c0*y, c1*y, s0*y, s1*y}
    float4 C[ND];   // mixes 2,3 u's
    float4 D[ND];   // mixes 2,3 cos*y/sin*y
    float4 P[ND];   // {P0,P1,P2,P3}
};                                    // 40960 B
struct Reduce {                       // live after pair loop
    u64   red[16][32][2];             // 8192 B
    float sred[4][HD];                // 2048 B
};
struct TailSm {                       // live in tail (last block per b)
    float h1[NCHv * HD];
    float h2[HD];
    float h3[HD];
    float sred[4][HD];
    float out5[NCHv * NMIXv][4];
};                                    // ~4.3 KB

// ---------------- the one kernel ----------------
// grid (16 tiles, 3 ch, 8 batch), 512 threads.
//   exp arg: -(|ua-uc|^2) = Pa + Pc + (2u0a)*u0c + (2u1a)*u1c
//   u = x*istd*ALPHA, P = -(u0^2+u1^2), ALPHA^2 = 0.5*(2pi)^2*log2(e)
//   K*y contribution: ex2(s) * (ca*(cc*y) + sa*(sc*y))
// Last arriving block per batch b runs the tail (layers 2..5) inline.
__global__ void __launch_bounds__(512, 3) k_all(
    const float* __restrict__ xc, const float* __restrict__ yc,
    const float* __restrict__ mu, const float* __restrict__ istd,
    const float* __restrict__ w1p, const float* __restrict__ b1p,
    const float* __restrict__ w2, const float* __restrict__ b2,
    const float* __restrict__ w3, const float* __restrict__ b3,
    const float* __restrict__ w4, const float* __restrict__ b4,
    const float* __restrict__ w5, const float* __restrict__ b5,
    float* __restrict__ out)
{
    __shared__ union { Tables t; Reduce r; TailSm tl; } sm;   // 40960 B
    __shared__ float sy[ND];                                   //  2048 B
    __shared__ int s_last;

    const int tile = blockIdx.x, k = blockIdx.y, b = blockIdx.z;
    const int tid = threadIdx.x;

    const float PI2   = 6.2831853071795864f;
    const float ALPHA = 5.3364454f;   // 2pi*sqrt(0.5*log2(e))

    // ---- build full c-table (one point per thread) ----
    {
        const int c = tid;
        const float x0 = xc[((b * ND + c) * 2 + 0) * NCHv + k];
        const float x1 = xc[((b * ND + c) * 2 + 1) * NCHv + k];
        const float y  = yc[(b * ND + c) * NCHv + k];
        float U0[4], U1[4], CO[4], SI[4], P[4];
        #pragma unroll
        for (int m = 0; m < NMIXv; m++) {
            const float u0 = x0 * istd[2 * m + 0] * ALPHA;
            const float u1 = x1 * istd[2 * m + 1] * ALPHA;
            float t = fmaf(x0, mu[2 * m + 0], x1 * mu[2 * m + 1]);
            t -= rintf(t);
            float sn, cn; __sincosf(PI2 * t, &sn, &cn);
            U0[m] = u0; U1[m] = u1; CO[m] = cn * y; SI[m] = sn * y;
            P[m] = -fmaf(u0, u0, u1 * u1);
        }
        sm.t.A[c] = make_float4(U0[0], U0[1], U1[0], U1[1]);
        sm.t.B[c] = make_float4(CO[0], CO[1], SI[0], SI[1]);
        sm.t.C[c] = make_float4(U0[2], U0[3], U1[2], U1[3]);
        sm.t.D[c] = make_float4(CO[2], CO[3], SI[2], SI[3]);
        sm.t.P[c] = make_float4(P[0], P[1], P[2], P[3]);
        sy[c] = y;
    }

    // ---- per-lane A-side values ----
    const int al = tid & 31;
    const int cs = tid >> 5;          // c-split 0..15, uniform per warp
    const int a  = tile * 32 + al;

    u64 a0[2], a1[2], ca[2], sa[2], pa[2];
    {
        const float x0 = xc[((b * ND + a) * 2 + 0) * NCHv + k];
        const float x1 = xc[((b * ND + a) * 2 + 1) * NCHv + k];
        float U0[4], U1[4], CO[4], SI[4], P[4];
        #pragma unroll
        for (int m = 0; m < NMIXv; m++) {
            const float u0 = x0 * istd[2 * m + 0] * ALPHA;
            const float u1 = x1 * istd[2 * m + 1] * ALPHA;
            float t = fmaf(x0, mu[2 * m + 0], x1 * mu[2 * m + 1]);
            t -= rintf(t);
            float sn, cn; __sincosf(PI2 * t, &sn, &cn);
            U0[m] = 2.0f * u0; U1[m] = 2.0f * u1; CO[m] = cn; SI[m] = sn;
            P[m] = -fmaf(u0, u0, u1 * u1);
        }
        #pragma unroll
        for (int p = 0; p < 2; p++) {
            a0[p] = pack2(U0[2*p], U0[2*p+1]);
            a1[p] = pack2(U1[2*p], U1[2*p+1]);
            ca[p] = pack2(CO[2*p], CO[2*p+1]);
            sa[p] = pack2(SI[2*p], SI[2*p+1]);
            pa[p] = pack2(P[2*p],  P[2*p+1]);
        }
    }
    __syncthreads();

    // ---- pair loop: warp = 32 a-lanes, uniform c-split (broadcast LDS) ----
    u64 acc0 = 0, acc1 = 0;

    #pragma unroll 2
    for (int c = cs; c < ND; c += 16) {
        u64 pc0, pc1;
        lds2(pc0, pc1, &sm.t.P[c]);
        // mix pair 0
        {
            u64 u0x2, u1x2, cyx2, syx2;
            lds2(u0x2, u1x2, &sm.t.A[c]);
            lds2(cyx2, syx2, &sm.t.B[c]);
            u64 s = add2(pa[0], pc0);
            s = fma2(u0x2, a0[0], s);
            s = fma2(u1x2, a1[0], s);
            u64 cvy = mul2(syx2, sa[0]);
            cvy = fma2(cyx2, ca[0], cvy);
            float s0, s1; unpack2(s0, s1, s);
            acc0 = fma2(pack2(ex2f(s0), ex2f(s1)), cvy, acc0);
        }
        // mix pair 1
        {
            u64 u0x2, u1x2, cyx2, syx2;
            lds2(u0x2, u1x2, &sm.t.C[c]);
            lds2(cyx2, syx2, &sm.t.D[c]);
            u64 s = add2(pa[1], pc1);
            s = fma2(u0x2, a0[1], s);
            s = fma2(u1x2, a1[1], s);
            u64 cvy = mul2(syx2, sa[1]);
            cvy = fma2(cyx2, ca[1], cvy);
            float s0, s1; unpack2(s0, s1, s);
            acc1 = fma2(pack2(ex2f(s0), ex2f(s1)), cvy, acc1);
        }
    }

    // tables dead; red/sred alias them — barrier first
    __syncthreads();
    sm.r.red[cs][al][0] = acc0;
    sm.r.red[cs][al][1] = acc1;
    __syncthreads();

    // ---- reduce 16 c-splits, add zitter ----
    if (tid < 64) {
        const int lane = tid >> 1, p = tid & 1;
        u64 f = sm.r.red[0][lane][p];
        #pragma unroll
        for (int s = 1; s < 16; s++) f = add2(f, sm.r.red[s][lane][p]);
        const float zy = 1.0e-4f * sy[tile * 32 + lane];
        f = add2(f, pack2(zy, zy));
        sm.r.red[0][lane][p] = f;
    }
    __syncthreads();

    // ---- fused layer 1 on this tile's 32 a's ----
    {
        const int j = tid & 127, q = tid >> 7;
        const float wv0 = w1p[j * 5 + 0], wv1 = w1p[j * 5 + 1], wv2 = w1p[j * 5 + 2];
        const float wv3 = w1p[j * 5 + 3], wv4 = w1p[j * 5 + 4], bb = b1p[j];
        float acc = 0.f;
        #pragma unroll
        for (int aa = 0; aa < 8; aa++) {
            const int lane = q * 8 + aa;
            const float4 f = *(const float4*)&sm.r.red[0][lane][0]; // (m0..m3)
            const float y = sy[tile * 32 + lane];
            float h = fmaf(wv0, f.x, bb);
            h = fmaf(wv1, f.y, h);
            h = fmaf(wv2, f.z, h);
            h = fmaf(wv3, f.w, h);
            h = fmaf(wv4, y, h);
            acc += fmaxf(h, 0.f);
        }
        sm.r.sred[q][j] = acc;
    }
    __syncthreads();
    if (tid < HD) {
        g_part[((b * NCHv + k) * NTILE + tile) * HD + tid] =
            sm.r.sred[0][tid] + sm.r.sred[1][tid] + sm.r.sred[2][tid] + sm.r.sred[3][tid];
    }
    __syncthreads();

    // ---- arrival: last of the 48 blocks for this b runs the tail ----
    if (tid == 0) {
        __threadfence();
        const int old = atomicAdd(&g_cnt[b], 1);
        s_last = (old == NCHv * NTILE - 1) ? 1 : 0;
    }
    __syncthreads();
    if (!s_last) return;
    __threadfence();   // acquire: see all other blocks' g_part writes

    // =================== TAIL (one block per b) ===================
    const int j = tid & 127, q = tid >> 7;

    // reduce 16 tile-partials per (k,j) -> h1 (mean over 512 a)
    if (tid < NCHv * HD) {
        const int kk = tid >> 7, jj = tid & 127;
        const float* p = &g_part[((b * NCHv + kk) * NTILE) * HD + jj];
        float acc = 0.f;
        #pragma unroll
        for (int t = 0; t < NTILE; t++) acc += p[t * HD];
        sm.tl.h1[tid] = acc * (1.0f / 512.0f);
    }
    __syncthreads();

    // layer 2: 384 -> 128
    {
        float acc0 = 0.f, acc1 = 0.f;
        const float4* wr = (const float4*)(w2 + j * (NCHv * HD) + q * 96);
        const float4* xv = (const float4*)(sm.tl.h1 + q * 96);
        #pragma unroll 12
        for (int i = 0; i < 24; i += 2) {
            { const float4 w = wr[i], x = xv[i];
              acc0 = fmaf(w.x, x.x, acc0); acc0 = fmaf(w.y, x.y, acc0);
              acc0 = fmaf(w.z, x.z, acc0); acc0 = fmaf(w.w, x.w, acc0); }
            { const float4 w = wr[i+1], x = xv[i+1];
              acc1 = fmaf(w.x, x.x, acc1); acc1 = fmaf(w.y, x.y, acc1);
              acc1 = fmaf(w.z, x.z, acc1); acc1 = fmaf(w.w, x.w, acc1); }
        }
        sm.tl.sred[q][j] = acc0 + acc1;
        __syncthreads();
        if (tid < HD)
            sm.tl.h2[tid] = fmaxf(sm.tl.sred[0][tid] + sm.tl.sred[1][tid]
                                  + sm.tl.sred[2][tid] + sm.tl.sred[3][tid]
                                  + b2[tid], 0.f);
        __syncthreads();
    }

    // layer 3: 128 -> 128
    {
        float acc0 = 0.f;
        const float4* wr = (const float4*)(w3 + j * HD + q * 32);
        const float4* xv = (const float4*)(sm.tl.h2 + q * 32);
        #pragma unroll
        for (int i = 0; i < 8; i++) {
            const float4 w = wr[i], x = xv[i];
            acc0 = fmaf(w.x, x.x, acc0); acc0 = fmaf(w.y, x.y, acc0);
            acc0 = fmaf(w.z, x.z, acc0); acc0 = fmaf(w.w, x.w, acc0);
        }
        sm.tl.sred[q][j] = acc0;
        __syncthreads();
        if (tid < HD)
            sm.tl.h3[tid] = fmaxf(sm.tl.sred[0][tid] + sm.tl.sred[1][tid]
                                  + sm.tl.sred[2][tid] + sm.tl.sred[3][tid]
                                  + b3[tid], 0.f);
        __syncthreads();
    }

    // layer 4: 128 -> 128 (into h2)
    {
        float acc0 = 0.f;
        const float4* wr = (const float4*)(w4 + j * HD + q * 32);
        const float4* xv = (const float4*)(sm.tl.h3 + q * 32);
        #pragma unroll
        for (int i = 0; i < 8; i++) {
            const float4 w = wr[i], x = xv[i];
            acc0 = fmaf(w.x, x.x, acc0); acc0 = fmaf(w.y, x.y, acc0);
            acc0 = fmaf(w.z, x.z, acc0); acc0 = fmaf(w.w, x.w, acc0);
        }
        sm.tl.sred[q][j] = acc0;
        __syncthreads();
        if (tid < HD)
            sm.tl.h2[tid] = fmaxf(sm.tl.sred[0][tid] + sm.tl.sred[1][tid]
                                  + sm.tl.sred[2][tid] + sm.tl.sred[3][tid]
                                  + b4[tid], 0.f);
        __syncthreads();
    }

    // layer 5: 128 -> 12
    if (tid < NCHv * NMIXv * 4) {
        const int j5 = tid >> 2, p = tid & 3;
        float acc = 0.f;
        const float4* wr = (const float4*)(w5 + j5 * HD + p * 32);
        const float4* xv = (const float4*)(sm.tl.h2 + p * 32);
        #pragma unroll
        for (int i = 0; i < 8; i++) {
            const float4 w = wr[i], x = xv[i];
            acc = fmaf(w.x, x.x, acc); acc = fmaf(w.y, x.y, acc);
            acc = fmaf(w.z, x.z, acc); acc = fmaf(w.w, x.w, acc);
        }
        sm.tl.out5[j5][p] = acc;
    }
    __syncthreads();
    if (tid < NCHv * NMIXv)
        out[b * (NCHv * NMIXv) + tid] =
            sm.tl.out5[tid][0] + sm.tl.out5[tid][1] + sm.tl.out5[tid][2]
            + sm.tl.out5[tid][3] + b5[tid];

    // reset counter for next graph replay
    __syncthreads();
    if (tid == 0) g_cnt[b] = 0;
}

// ---------------- launch ----------------
extern "C" void kernel_launch(void* const* d_in, const int* in_sizes, int n_in,
                              void* d_out, int out_size)
{
    const float* xc   = (const float*)d_in[0];
    const float* yc   = (const float*)d_in[1];
    const float* mu   = (const float*)d_in[2];
    const float* istd = (const float*)d_in[3];
    const float* w1   = (const float*)d_in[4];
    const float* b1   = (const float*)d_in[5];
    const float* w2   = (const float*)d_in[6];
    const float* b2   = (const float*)d_in[7];
    const float* w3   = (const float*)d_in[8];
    const float* b3   = (const float*)d_in[9];
    const float* w4   = (const float*)d_in[10];
    const float* b4   = (const float*)d_in[11];
    const float* w5   = (const float*)d_in[12];
    const float* b5   = (const float*)d_in[13];
    float* out = (float*)d_out;

    dim3 g1(NTILE, NCHv, NBv);   // 16 x 3 x 8 = 384 blocks, 512 threads
    k_all<<<g1, 512>>>(xc, yc, mu, istd, w1, b1,
                       w2, b2, w3, b3, w4, b4, w5, b5, out);
}

// round 6
// speedup vs baseline: 1.4516x; 1.4516x over previous
#include <cuda_runtime.h>

#define NBv   8
#define ND    512
#define NCHv  3
#define NMIXv 4
#define HD    128
#define NTILE 16          // 512 / 32 a-tiles
#define NARRIVE (NCHv * NTILE)   // 48 work blocks per batch

typedef unsigned long long u64;

// ---------------- device scratch ----------------
__device__ float g_part[NBv * NCHv * NTILE * HD];  // per-(b,k,tile) layer1 partials
__device__ int   g_cnt[NBv];                        // arrival counters (zero-init)
__device__ float g_sink[512];                       // prefetch sink (deterministic)

// ---------------- f32x2 helpers (sm_100a packed math) ----------------
__device__ __forceinline__ u64 fma2(u64 a, u64 b, u64 c) {
    u64 d; asm("fma.rn.f32x2 %0,%1,%2,%3;" : "=l"(d) : "l"(a), "l"(b), "l"(c)); return d;
}
__device__ __forceinline__ u64 add2(u64 a, u64 b) {
    u64 d; asm("add.rn.f32x2 %0,%1,%2;" : "=l"(d) : "l"(a), "l"(b)); return d;
}
__device__ __forceinline__ u64 mul2(u64 a, u64 b) {
    u64 d; asm("mul.rn.f32x2 %0,%1,%2;" : "=l"(d) : "l"(a), "l"(b)); return d;
}
__device__ __forceinline__ u64 pack2(float lo, float hi) {
    u64 d; asm("mov.b64 %0,{%1,%2};" : "=l"(d) : "f"(lo), "f"(hi)); return d;
}
__device__ __forceinline__ void unpack2(float& lo, float& hi, u64 v) {
    asm("mov.b64 {%0,%1},%2;" : "=f"(lo), "=f"(hi) : "l"(v));
}
__device__ __forceinline__ float ex2f(float x) {
    float r; asm("ex2.approx.f32 %0, %1;" : "=f"(r) : "f"(x)); return r;
}
__device__ __forceinline__ void lds2(u64& lo, u64& hi, const float4* p) {
    unsigned a = (unsigned)__cvta_generic_to_shared(p);
    asm volatile("ld.shared.v2.b64 {%0,%1}, [%2];" : "=l"(lo), "=l"(hi) : "r"(a));
}
__device__ __forceinline__ u64 lds1(const void* p) {
    unsigned a = (unsigned)__cvta_generic_to_shared(p);
    u64 v; asm volatile("ld.shared.b64 %0, [%1];" : "=l"(v) : "r"(a));
    return v;
}

// ---------------- shared-memory overlays ----------------
struct Tables {                       // live during pair loop only
    float4 A[ND], B[ND], C[ND], D[ND], P[ND];     // 40960 B
};
struct Reduce {                       // live after pair loop
    u64   red[16][32][2];             // 8192 B
    float sred[4][HD];                // 2048 B
};
struct TailSm {                       // live only in tail blocks
    float h1[NCHv * HD];
    float h2[HD];
    float h3[HD];
    float sred[4][HD];
    float out5[NCHv * NMIXv][4];
};

// ---------------- the one kernel ----------------
// grid (17, 3, 8), 512 threads.
//   blockIdx.x < 16             : pair+layer1 work block (R4 k_pair, verbatim)
//   blockIdx.x == 16 && k == 0  : tail block for batch b (prefetch, spin, layers 2..5)
//   blockIdx.x == 16 && k != 0  : exits immediately
__global__ void __launch_bounds__(512, 3) k_all(
    const float* __restrict__ xc, const float* __restrict__ yc,
    const float* __restrict__ mu, const float* __restrict__ istd,
    const float* __restrict__ w1p, const float* __restrict__ b1p,
    const float* __restrict__ w2, const float* __restrict__ b2,
    const float* __restrict__ w3, const float* __restrict__ b3,
    const float* __restrict__ w4, const float* __restrict__ b4,
    const float* __restrict__ w5, const float* __restrict__ b5,
    float* __restrict__ out)
{
    __shared__ union { Tables t; Reduce r; TailSm tl; } sm;   // 40960 B
    __shared__ float2 syy[ND];                                 //  4096 B

    const int tile = blockIdx.x, k = blockIdx.y, b = blockIdx.z;
    const int tid = threadIdx.x;

    if (tile == NTILE) {
        // =================== TAIL BLOCK (one per b) ===================
        if (k != 0) return;

        // ---- prefetch all layer 2..5 weights while work blocks run ----
        {
            float4 jk = make_float4(0.f, 0.f, 0.f, 0.f);
            const float4* p2 = (const float4*)w2;   // 12288 float4
            for (int i = tid; i < 12288; i += 512) {
                const float4 v = p2[i];
                jk.x += v.x; jk.y += v.y; jk.z += v.z; jk.w += v.w;
            }
            const float4* p3 = (const float4*)w3;   // 4096
            const float4* p4 = (const float4*)w4;   // 4096
            for (int i = tid; i < 4096; i += 512) {
                const float4 v3 = p3[i], v4 = p4[i];
                jk.x += v3.x + v4.x; jk.y += v3.y + v4.y;
                jk.z += v3.z + v4.z; jk.w += v3.w + v4.w;
            }
            const float4* p5 = (const float4*)w5;   // 384
            if (tid < 384) {
                const float4 v = p5[tid];
                jk.x += v.x; jk.y += v.y; jk.z += v.z; jk.w += v.w;
            }
            g_sink[tid] = jk.x + jk.y + jk.z + jk.w;   // deterministic
        }

        // ---- spin until all 48 work blocks for this b have arrived ----
        if (tid == 0) {
            while (*(volatile int*)&g_cnt[b] != NARRIVE) __nanosleep(128);
        }
        __syncthreads();
        __threadfence();   // acquire: see all work blocks' g_part stores

        const int j = tid & 127, q = tid >> 7;

        // reduce 16 tile-partials per (k,j) -> h1 (mean over 512 a)
        if (tid < NCHv * HD) {
            const int kk = tid >> 7, jj = tid & 127;
            const float* p = &g_part[((b * NCHv + kk) * NTILE) * HD + jj];
            float acc = 0.f;
            #pragma unroll
            for (int t = 0; t < NTILE; t++) acc += p[t * HD];
            sm.tl.h1[tid] = acc * (1.0f / 512.0f);
        }
        __syncthreads();

        // layer 2: 384 -> 128
        {
            float acc0 = 0.f, acc1 = 0.f;
            const float4* wr = (const float4*)(w2 + j * (NCHv * HD) + q * 96);
            const float4* xv = (const float4*)(sm.tl.h1 + q * 96);
            #pragma unroll 12
            for (int i = 0; i < 24; i += 2) {
                { const float4 w = wr[i], x = xv[i];
                  acc0 = fmaf(w.x, x.x, acc0); acc0 = fmaf(w.y, x.y, acc0);
                  acc0 = fmaf(w.z, x.z, acc0); acc0 = fmaf(w.w, x.w, acc0); }
                { const float4 w = wr[i+1], x = xv[i+1];
                  acc1 = fmaf(w.x, x.x, acc1); acc1 = fmaf(w.y, x.y, acc1);
                  acc1 = fmaf(w.z, x.z, acc1); acc1 = fmaf(w.w, x.w, acc1); }
            }
            sm.tl.sred[q][j] = acc0 + acc1;
            __syncthreads();
            if (tid < HD)
                sm.tl.h2[tid] = fmaxf(sm.tl.sred[0][tid] + sm.tl.sred[1][tid]
                                      + sm.tl.sred[2][tid] + sm.tl.sred[3][tid]
                                      + b2[tid], 0.f);
            __syncthreads();
        }

        // layer 3: 128 -> 128
        {
            float acc0 = 0.f;
            const float4* wr = (const float4*)(w3 + j * HD + q * 32);
            const float4* xv = (const float4*)(sm.tl.h2 + q * 32);
            #pragma unroll
            for (int i = 0; i < 8; i++) {
                const float4 w = wr[i], x = xv[i];
                acc0 = fmaf(w.x, x.x, acc0); acc0 = fmaf(w.y, x.y, acc0);
                acc0 = fmaf(w.z, x.z, acc0); acc0 = fmaf(w.w, x.w, acc0);
            }
            sm.tl.sred[q][j] = acc0;
            __syncthreads();
            if (tid < HD)
                sm.tl.h3[tid] = fmaxf(sm.tl.sred[0][tid] + sm.tl.sred[1][tid]
                                      + sm.tl.sred[2][tid] + sm.tl.sred[3][tid]
                                      + b3[tid], 0.f);
            __syncthreads();
        }

        // layer 4: 128 -> 128 (into h2)
        {
            float acc0 = 0.f;
            const float4* wr = (const float4*)(w4 + j * HD + q * 32);
            const float4* xv = (const float4*)(sm.tl.h3 + q * 32);
            #pragma unroll
            for (int i = 0; i < 8; i++) {
                const float4 w = wr[i], x = xv[i];
                acc0 = fmaf(w.x, x.x, acc0); acc0 = fmaf(w.y, x.y, acc0);
                acc0 = fmaf(w.z, x.z, acc0); acc0 = fmaf(w.w, x.w, acc0);
            }
            sm.tl.sred[q][j] = acc0;
            __syncthreads();
            if (tid < HD)
                sm.tl.h2[tid] = fmaxf(sm.tl.sred[0][tid] + sm.tl.sred[1][tid]
                                      + sm.tl.sred[2][tid] + sm.tl.sred[3][tid]
                                      + b4[tid], 0.f);
            __syncthreads();
        }

        // layer 5: 128 -> 12
        if (tid < NCHv * NMIXv * 4) {
            const int j5 = tid >> 2, p = tid & 3;
            float acc = 0.f;
            const float4* wr = (const float4*)(w5 + j5 * HD + p * 32);
            const float4* xv = (const float4*)(sm.tl.h2 + p * 32);
            #pragma unroll
            for (int i = 0; i < 8; i++) {
                const float4 w = wr[i], x = xv[i];
                acc = fmaf(w.x, x.x, acc); acc = fmaf(w.y, x.y, acc);
                acc = fmaf(w.z, x.z, acc); acc = fmaf(w.w, x.w, acc);
            }
            sm.tl.out5[j5][p] = acc;
        }
        __syncthreads();
        if (tid < NCHv * NMIXv)
            out[b * (NCHv * NMIXv) + tid] =
                sm.tl.out5[tid][0] + sm.tl.out5[tid][1] + sm.tl.out5[tid][2]
                + sm.tl.out5[tid][3] + b5[tid];

        // reset counter for next graph replay (after all g_part reads)
        __syncthreads();
        if (tid == 0) g_cnt[b] = 0;
        return;
    }

    // =================== WORK BLOCK (R4 k_pair, verbatim) ===================
    const float PI2   = 6.2831853071795864f;
    const float ALPHA = 5.3364454f;   // 2pi*sqrt(0.5*log2(e))

    // ---- build full c-table (one point per thread) ----
    {
        const int c = tid;
        const float x0 = xc[((b * ND + c) * 2 + 0) * NCHv + k];
        const float x1 = xc[((b * ND + c) * 2 + 1) * NCHv + k];
        const float y  = yc[(b * ND + c) * NCHv + k];
        float U0[4], U1[4], CO[4], SI[4], P[4];
        #pragma unroll
        for (int m = 0; m < NMIXv; m++) {
            const float u0 = x0 * istd[2 * m + 0] * ALPHA;
            const float u1 = x1 * istd[2 * m + 1] * ALPHA;
            float t = fmaf(x0, mu[2 * m + 0], x1 * mu[2 * m + 1]);
            t -= rintf(t);
            float sn, cn; __sincosf(PI2 * t, &sn, &cn);
            U0[m] = u0; U1[m] = u1; CO[m] = cn; SI[m] = sn;
            P[m] = -fmaf(u0, u0, u1 * u1);
        }
        sm.t.A[c] = make_float4(U0[0], U0[1], U1[0], U1[1]);
        sm.t.B[c] = make_float4(CO[0], CO[1], SI[0], SI[1]);
        sm.t.C[c] = make_float4(U0[2], U0[3], U1[2], U1[3]);
        sm.t.D[c] = make_float4(CO[2], CO[3], SI[2], SI[3]);
        sm.t.P[c] = make_float4(P[0], P[1], P[2], P[3]);
        syy[c] = make_float2(y, y);
    }

    // ---- per-lane A-side values ----
    const int al = tid & 31;
    const int cs = tid >> 5;          // c-split 0..15, uniform per warp
    const int a  = tile * 32 + al;

    u64 a0[2], a1[2], ca[2], sa[2], pa[2];
    {
        const float x0 = xc[((b * ND + a) * 2 + 0) * NCHv + k];
        const float x1 = xc[((b * ND + a) * 2 + 1) * NCHv + k];
        float U0[4], U1[4], CO[4], SI[4], P[4];
        #pragma unroll
        for (int m = 0; m < NMIXv; m++) {
            const float u0 = x0 * istd[2 * m + 0] * ALPHA;
            const float u1 = x1 * istd[2 * m + 1] * ALPHA;
            float t = fmaf(x0, mu[2 * m + 0], x1 * mu[2 * m + 1]);
            t -= rintf(t);
            float sn, cn; __sincosf(PI2 * t, &sn, &cn);
            U0[m] = 2.0f * u0; U1[m] = 2.0f * u1; CO[m] = cn; SI[m] = sn;
            P[m] = -fmaf(u0, u0, u1 * u1);
        }
        #pragma unroll
        for (int p = 0; p < 2; p++) {
            a0[p] = pack2(U0[2*p], U0[2*p+1]);
            a1[p] = pack2(U1[2*p], U1[2*p+1]);
            ca[p] = pack2(CO[2*p], CO[2*p+1]);
            sa[p] = pack2(SI[2*p], SI[2*p+1]);
            pa[p] = pack2(P[2*p],  P[2*p+1]);
        }
    }
    __syncthreads();

    // ---- pair loop: warp = 32 a-lanes, uniform c-split (broadcast LDS) ----
    u64 acc0 = 0, acc1 = 0;

    #pragma unroll 2
    for (int c = cs; c < ND; c += 16) {
        const u64 yv = lds1(&syy[c]);
        // mix pair 0
        {
            u64 u0x2, u1x2, cox2, six2;
            lds2(u0x2, u1x2, &sm.t.A[c]);
            lds2(cox2, six2, &sm.t.B[c]);
            const u64 pc = lds1(&sm.t.P[c].x);
            u64 s = add2(pa[0], pc);
            s = fma2(u0x2, a0[0], s);
            s = fma2(u1x2, a1[0], s);
            u64 cv = mul2(six2, sa[0]);
            cv = fma2(cox2, ca[0], cv);
            float s0, s1; unpack2(s0, s1, s);
            acc0 = fma2(mul2(pack2(ex2f(s0), ex2f(s1)), cv), yv, acc0);
        }
        // mix pair 1
        {
            u64 u0x2, u1x2, cox2, six2;
            lds2(u0x2, u1x2, &sm.t.C[c]);
            lds2(cox2, six2, &sm.t.D[c]);
            const u64 pc = lds1(&sm.t.P[c].z);
            u64 s = add2(pa[1], pc);
            s = fma2(u0x2, a0[1], s);
            s = fma2(u1x2, a1[1], s);
            u64 cv = mul2(six2, sa[1]);
            cv = fma2(cox2, ca[1], cv);
            float s0, s1; unpack2(s0, s1, s);
            acc1 = fma2(mul2(pack2(ex2f(s0), ex2f(s1)), cv), yv, acc1);
        }
    }

    // tables dead; red/sred alias them — barrier first
    __syncthreads();
    sm.r.red[cs][al][0] = acc0;
    sm.r.red[cs][al][1] = acc1;
    __syncthreads();

    // ---- reduce 16 c-splits, add zitter ----
    if (tid < 64) {
        const int lane = tid >> 1, p = tid & 1;
        u64 f = sm.r.red[0][lane][p];
        #pragma unroll
        for (int s = 1; s < 16; s++) f = add2(f, sm.r.red[s][lane][p]);
        const float ya = syy[tile * 32 + lane].x;
        const float zy = 1.0e-4f * ya;
        f = add2(f, pack2(zy, zy));
        sm.r.red[0][lane][p] = f;
    }
    __syncthreads();

    // ---- fused layer 1 on this tile's 32 a's ----
    {
        const int j = tid & 127, q = tid >> 7;
        const float wv0 = w1p[j * 5 + 0], wv1 = w1p[j * 5 + 1], wv2 = w1p[j * 5 + 2];
        const float wv3 = w1p[j * 5 + 3], wv4 = w1p[j * 5 + 4], bb = b1p[j];
        float acc = 0.f;
        #pragma unroll
        for (int aa = 0; aa < 8; aa++) {
            const int lane = q * 8 + aa;
            const float4 f = *(const float4*)&sm.r.red[0][lane][0]; // (m0..m3)
            const float y = syy[tile * 32 + lane].x;
            float h = fmaf(wv0, f.x, bb);
            h = fmaf(wv1, f.y, h);
            h = fmaf(wv2, f.z, h);
            h = fmaf(wv3, f.w, h);
            h = fmaf(wv4, y, h);
            acc += fmaxf(h, 0.f);
        }
        sm.r.sred[q][j] = acc;
    }
    __syncthreads();
    if (tid < HD) {
        g_part[((b * NCHv + k) * NTILE + tile) * HD + tid] =
            sm.r.sred[0][tid] + sm.r.sred[1][tid] + sm.r.sred[2][tid] + sm.r.sred[3][tid];
    }

    // ---- release: publish g_part, then signal arrival ----
    __threadfence();
    __syncthreads();
    if (tid == 0) atomicAdd(&g_cnt[b], 1);
}

// ---------------- launch ----------------
extern "C" void kernel_launch(void* const* d_in, const int* in_sizes, int n_in,
                              void* d_out, int out_size)
{
    const float* xc   = (const float*)d_in[0];
    const float* yc   = (const float*)d_in[1];
    const float* mu   = (const float*)d_in[2];
    const float* istd = (const float*)d_in[3];
    const float* w1   = (const float*)d_in[4];
    const float* b1   = (const float*)d_in[5];
    const float* w2   = (const float*)d_in[6];
    const float* b2   = (const float*)d_in[7];
    const float* w3   = (const float*)d_in[8];
    const float* b3   = (const float*)d_in[9];
    const float* w4   = (const float*)d_in[10];
    const float* b4   = (const float*)d_in[11];
    const float* w5   = (const float*)d_in[12];
    const float* b5   = (const float*)d_in[13];
    float* out = (float*)d_out;

    dim3 g1(NTILE + 1, NCHv, NBv);   // 17 x 3 x 8 = 408 blocks, 512 threads
    k_all<<<g1, 512>>>(xc, yc, mu, istd, w1, b1,
                       w2, b2, w3, b3, w4, b4, w5, b5, out);
}

// round 7
// speedup vs baseline: 1.5556x; 1.0716x over previous
#include <cuda_runtime.h>

#define NBv   8
#define ND    512
#define NCHv  3
#define NMIXv 4
#define HD    128
#define NTILE 16
#define NARRIVE (NCHv * NTILE)   // 48 work blocks per batch

typedef unsigned long long u64;

// ---------------- device scratch ----------------
__device__ float g_part[NBv * NCHv * NTILE * HD];
__device__ int   g_cnt[NBv];
__device__ float g_sink[512];

// ---------------- f32x2 helpers ----------------
__device__ __forceinline__ u64 fma2(u64 a, u64 b, u64 c) {
    u64 d; asm("fma.rn.f32x2 %0,%1,%2,%3;" : "=l"(d) : "l"(a), "l"(b), "l"(c)); return d;
}
__device__ __forceinline__ u64 add2(u64 a, u64 b) {
    u64 d; asm("add.rn.f32x2 %0,%1,%2;" : "=l"(d) : "l"(a), "l"(b)); return d;
}
__device__ __forceinline__ u64 mul2(u64 a, u64 b) {
    u64 d; asm("mul.rn.f32x2 %0,%1,%2;" : "=l"(d) : "l"(a), "l"(b)); return d;
}
__device__ __forceinline__ u64 pack2(float lo, float hi) {
    u64 d; asm("mov.b64 %0,{%1,%2};" : "=l"(d) : "f"(lo), "f"(hi)); return d;
}
__device__ __forceinline__ void unpack2(float& lo, float& hi, u64 v) {
    asm("mov.b64 {%0,%1},%2;" : "=f"(lo), "=f"(hi) : "l"(v));
}
__device__ __forceinline__ float ex2f(float x) {
    float r; asm("ex2.approx.f32 %0, %1;" : "=f"(r) : "f"(x)); return r;
}

// ---------------- shared-memory overlays ----------------
struct Tables {
    float4 A[ND];   // {u0m0, u0m1, u1m0, u1m1}
    float4 B[ND];   // {c0*y, c1*y, s0*y, s1*y}
    float4 C[ND];   // mixes 2,3 u's
    float4 D[ND];   // mixes 2,3 c*y / s*y
    float4 P[ND];   // {P0,P1,P2,P3}
};                                    // 40960 B
struct Reduce {
    u64   red[16][32][2];             // 8192 B
    float sred[4][HD];                // 2048 B
};
struct TailSm {
    float h1[NCHv * HD];
    float h2[HD];
    float h3[HD];
    float sred[4][HD];
    float out5[NCHv * NMIXv][4];
};

// ---------------- the one kernel ----------------
// grid (17, 3, 8), 512 threads.
//   blockIdx.x < 16            : pair + layer1 work block
//   blockIdx.x == 16 && k == 0 : tail block for batch b
//   blockIdx.x == 16 && k != 0 : exits
__global__ void __launch_bounds__(512, 3) k_all(
    const float* __restrict__ xc, const float* __restrict__ yc,
    const float* __restrict__ mu, const float* __restrict__ istd,
    const float* __restrict__ w1p, const float* __restrict__ b1p,
    const float* __restrict__ w2, const float* __restrict__ b2,
    const float* __restrict__ w3, const float* __restrict__ b3,
    const float* __restrict__ w4, const float* __restrict__ b4,
    const float* __restrict__ w5, const float* __restrict__ b5,
    float* __restrict__ out)
{
    __shared__ union { Tables t; Reduce r; TailSm tl; } sm;   // 40960 B
    __shared__ float sy[ND];                                   //  2048 B

    const int tile = blockIdx.x, k = blockIdx.y, b = blockIdx.z;
    const int tid = threadIdx.x;

    if (tile == NTILE) {
        // =================== TAIL BLOCK (one per b) ===================
        if (k != 0) return;

        // prefetch layer 2..5 weights while work blocks run
        {
            float4 jk = make_float4(0.f, 0.f, 0.f, 0.f);
            const float4* p2 = (const float4*)w2;
            for (int i = tid; i < 12288; i += 512) {
                const float4 v = p2[i];
                jk.x += v.x; jk.y += v.y; jk.z += v.z; jk.w += v.w;
            }
            const float4* p3 = (const float4*)w3;
            const float4* p4 = (const float4*)w4;
            for (int i = tid; i < 4096; i += 512) {
                const float4 v3 = p3[i], v4 = p4[i];
                jk.x += v3.x + v4.x; jk.y += v3.y + v4.y;
                jk.z += v3.z + v4.z; jk.w += v3.w + v4.w;
            }
            const float4* p5 = (const float4*)w5;
            if (tid < 384) {
                const float4 v = p5[tid];
                jk.x += v.x; jk.y += v.y; jk.z += v.z; jk.w += v.w;
            }
            g_sink[tid] = jk.x + jk.y + jk.z + jk.w;
        }

        if (tid == 0) {
            while (*(volatile int*)&g_cnt[b] != NARRIVE) __nanosleep(128);
        }
        __syncthreads();
        __threadfence();

        const int j = tid & 127, q = tid >> 7;

        if (tid < NCHv * HD) {
            const int kk = tid >> 7, jj = tid & 127;
            const float* p = &g_part[((b * NCHv + kk) * NTILE) * HD + jj];
            float acc = 0.f;
            #pragma unroll
            for (int t = 0; t < NTILE; t++) acc += p[t * HD];
            sm.tl.h1[tid] = acc * (1.0f / 512.0f);
        }
        __syncthreads();

        // layer 2: 384 -> 128
        {
            float acc0 = 0.f, acc1 = 0.f;
            const float4* wr = (const float4*)(w2 + j * (NCHv * HD) + q * 96);
            const float4* xv = (const float4*)(sm.tl.h1 + q * 96);
            #pragma unroll 12
            for (int i = 0; i < 24; i += 2) {
                { const float4 w = wr[i], x = xv[i];
                  acc0 = fmaf(w.x, x.x, acc0); acc0 = fmaf(w.y, x.y, acc0);
                  acc0 = fmaf(w.z, x.z, acc0); acc0 = fmaf(w.w, x.w, acc0); }
                { const float4 w = wr[i+1], x = xv[i+1];
                  acc1 = fmaf(w.x, x.x, acc1); acc1 = fmaf(w.y, x.y, acc1);
                  acc1 = fmaf(w.z, x.z, acc1); acc1 = fmaf(w.w, x.w, acc1); }
            }
            sm.tl.sred[q][j] = acc0 + acc1;
            __syncthreads();
            if (tid < HD)
                sm.tl.h2[tid] = fmaxf(sm.tl.sred[0][tid] + sm.tl.sred[1][tid]
                                      + sm.tl.sred[2][tid] + sm.tl.sred[3][tid]
                                      + b2[tid], 0.f);
            __syncthreads();
        }

        // layer 3
        {
            float acc0 = 0.f;
            const float4* wr = (const float4*)(w3 + j * HD + q * 32);
            const float4* xv = (const float4*)(sm.tl.h2 + q * 32);
            #pragma unroll
            for (int i = 0; i < 8; i++) {
                const float4 w = wr[i], x = xv[i];
                acc0 = fmaf(w.x, x.x, acc0); acc0 = fmaf(w.y, x.y, acc0);
                acc0 = fmaf(w.z, x.z, acc0); acc0 = fmaf(w.w, x.w, acc0);
            }
            sm.tl.sred[q][j] = acc0;
            __syncthreads();
            if (tid < HD)
                sm.tl.h3[tid] = fmaxf(sm.tl.sred[0][tid] + sm.tl.sred[1][tid]
                                      + sm.tl.sred[2][tid] + sm.tl.sred[3][tid]
                                      + b3[tid], 0.f);
            __syncthreads();
        }

        // layer 4
        {
            float acc0 = 0.f;
            const float4* wr = (const float4*)(w4 + j * HD + q * 32);
            const float4* xv = (const float4*)(sm.tl.h3 + q * 32);
            #pragma unroll
            for (int i = 0; i < 8; i++) {
                const float4 w = wr[i], x = xv[i];
                acc0 = fmaf(w.x, x.x, acc0); acc0 = fmaf(w.y, x.y, acc0);
                acc0 = fmaf(w.z, x.z, acc0); acc0 = fmaf(w.w, x.w, acc0);
            }
            sm.tl.sred[q][j] = acc0;
            __syncthreads();
            if (tid < HD)
                sm.tl.h2[tid] = fmaxf(sm.tl.sred[0][tid] + sm.tl.sred[1][tid]
                                      + sm.tl.sred[2][tid] + sm.tl.sred[3][tid]
                                      + b4[tid], 0.f);
            __syncthreads();
        }

        // layer 5
        if (tid < NCHv * NMIXv * 4) {
            const int j5 = tid >> 2, p = tid & 3;
            float acc = 0.f;
            const float4* wr = (const float4*)(w5 + j5 * HD + p * 32);
            const float4* xv = (const float4*)(sm.tl.h2 + p * 32);
            #pragma unroll
            for (int i = 0; i < 8; i++) {
                const float4 w = wr[i], x = xv[i];
                acc = fmaf(w.x, x.x, acc); acc = fmaf(w.y, x.y, acc);
                acc = fmaf(w.z, x.z, acc); acc = fmaf(w.w, x.w, acc);
            }
            sm.tl.out5[j5][p] = acc;
        }
        __syncthreads();
        if (tid < NCHv * NMIXv)
            out[b * (NCHv * NMIXv) + tid] =
                sm.tl.out5[tid][0] + sm.tl.out5[tid][1] + sm.tl.out5[tid][2]
                + sm.tl.out5[tid][3] + b5[tid];

        __syncthreads();
        if (tid == 0) g_cnt[b] = 0;
        return;
    }

    // =================== WORK BLOCK ===================
    const float PI2   = 6.2831853071795864f;
    const float ALPHA = 5.3364454f;   // 2pi*sqrt(0.5*log2(e))

    // ---- build full c-table (one point per thread), y folded into cos/sin ----
    {
        const int c = tid;
        const float x0 = xc[((b * ND + c) * 2 + 0) * NCHv + k];
        const float x1 = xc[((b * ND + c) * 2 + 1) * NCHv + k];
        const float y  = yc[(b * ND + c) * NCHv + k];
        float U0[4], U1[4], CO[4], SI[4], P[4];
        #pragma unroll
        for (int m = 0; m < NMIXv; m++) {
            const float u0 = x0 * istd[2 * m + 0] * ALPHA;
            const float u1 = x1 * istd[2 * m + 1] * ALPHA;
            float t = fmaf(x0, mu[2 * m + 0], x1 * mu[2 * m + 1]);
            t -= rintf(t);
            float sn, cn; __sincosf(PI2 * t, &sn, &cn);
            U0[m] = u0; U1[m] = u1; CO[m] = cn * y; SI[m] = sn * y;
            P[m] = -fmaf(u0, u0, u1 * u1);
        }
        sm.t.A[c] = make_float4(U0[0], U0[1], U1[0], U1[1]);
        sm.t.B[c] = make_float4(CO[0], CO[1], SI[0], SI[1]);
        sm.t.C[c] = make_float4(U0[2], U0[3], U1[2], U1[3]);
        sm.t.D[c] = make_float4(CO[2], CO[3], SI[2], SI[3]);
        sm.t.P[c] = make_float4(P[0], P[1], P[2], P[3]);
        sy[c] = y;
    }

    // ---- per-lane A-side values ----
    const int al = tid & 31;
    const int cs = tid >> 5;
    const int a  = tile * 32 + al;

    u64 a0[2], a1[2], ca[2], sa[2], pa[2];
    {
        const float x0 = xc[((b * ND + a) * 2 + 0) * NCHv + k];
        const float x1 = xc[((b * ND + a) * 2 + 1) * NCHv + k];
        float U0[4], U1[4], CO[4], SI[4], P[4];
        #pragma unroll
        for (int m = 0; m < NMIXv; m++) {
            const float u0 = x0 * istd[2 * m + 0] * ALPHA;
            const float u1 = x1 * istd[2 * m + 1] * ALPHA;
            float t = fmaf(x0, mu[2 * m + 0], x1 * mu[2 * m + 1]);
            t -= rintf(t);
            float sn, cn; __sincosf(PI2 * t, &sn, &cn);
            U0[m] = 2.0f * u0; U1[m] = 2.0f * u1; CO[m] = cn; SI[m] = sn;
            P[m] = -fmaf(u0, u0, u1 * u1);
        }
        #pragma unroll
        for (int p = 0; p < 2; p++) {
            a0[p] = pack2(U0[2*p], U0[2*p+1]);
            a1[p] = pack2(U1[2*p], U1[2*p+1]);
            ca[p] = pack2(CO[2*p], CO[2*p+1]);
            sa[p] = pack2(SI[2*p], SI[2*p+1]);
            pa[p] = pack2(P[2*p],  P[2*p+1]);
        }
    }
    __syncthreads();

    // ---- pair loop: plain C++ smem loads (schedulable), packed math ----
    u64 acc0 = 0, acc1 = 0;

    #pragma unroll 4
    for (int c = cs; c < ND; c += 16) {
        const float4 A = sm.t.A[c];
        const float4 B = sm.t.B[c];
        const float4 C = sm.t.C[c];
        const float4 D = sm.t.D[c];
        const float4 P = sm.t.P[c];
        // mix pair 0
        {
            u64 s = add2(pa[0], pack2(P.x, P.y));
            s = fma2(pack2(A.x, A.y), a0[0], s);
            s = fma2(pack2(A.z, A.w), a1[0], s);
            u64 cvy = mul2(pack2(B.z, B.w), sa[0]);
            cvy = fma2(pack2(B.x, B.y), ca[0], cvy);
            float s0, s1; unpack2(s0, s1, s);
            acc0 = fma2(pack2(ex2f(s0), ex2f(s1)), cvy, acc0);
        }
        // mix pair 1
        {
            u64 s = add2(pa[1], pack2(P.z, P.w));
            s = fma2(pack2(C.x, C.y), a0[1], s);
            s = fma2(pack2(C.z, C.w), a1[1], s);
            u64 cvy = mul2(pack2(D.z, D.w), sa[1]);
            cvy = fma2(pack2(D.x, D.y), ca[1], cvy);
            float s0, s1; unpack2(s0, s1, s);
            acc1 = fma2(pack2(ex2f(s0), ex2f(s1)), cvy, acc1);
        }
    }

    __syncthreads();   // tables dead; Reduce aliases them
    sm.r.red[cs][al][0] = acc0;
    sm.r.red[cs][al][1] = acc1;
    __syncthreads();

    // ---- reduce 16 c-splits, add zitter ----
    if (tid < 64) {
        const int lane = tid >> 1, p = tid & 1;
        u64 f = sm.r.red[0][lane][p];
        #pragma unroll
        for (int s = 1; s < 16; s++) f = add2(f, sm.r.red[s][lane][p]);
        const float zy = 1.0e-4f * sy[tile * 32 + lane];
        f = add2(f, pack2(zy, zy));
        sm.r.red[0][lane][p] = f;
    }
    __syncthreads();

    // ---- fused layer 1 on this tile's 32 a's ----
    {
        const int j = tid & 127, q = tid >> 7;
        const float wv0 = w1p[j * 5 + 0], wv1 = w1p[j * 5 + 1], wv2 = w1p[j * 5 + 2];
        const float wv3 = w1p[j * 5 + 3], wv4 = w1p[j * 5 + 4], bb = b1p[j];
        float acc = 0.f;
        #pragma unroll
        for (int aa = 0; aa < 8; aa++) {
            const int lane = q * 8 + aa;
            const float4 f = *(const float4*)&sm.r.red[0][lane][0];
            const float y = sy[tile * 32 + lane];
            float h = fmaf(wv0, f.x, bb);
            h = fmaf(wv1, f.y, h);
            h = fmaf(wv2, f.z, h);
            h = fmaf(wv3, f.w, h);
            h = fmaf(wv4, y, h);
            acc += fmaxf(h, 0.f);
        }
        sm.r.sred[q][j] = acc;
    }
    __syncthreads();
    if (tid < HD) {
        g_part[((b * NCHv + k) * NTILE + tile) * HD + tid] =
            sm.r.sred[0][tid] + sm.r.sred[1][tid] + sm.r.sred[2][tid] + sm.r.sred[3][tid];
    }

    __threadfence();
    __syncthreads();
    if (tid == 0) atomicAdd(&g_cnt[b], 1);
}

// ---------------- launch ----------------
extern "C" void kernel_launch(void* const* d_in, const int* in_sizes, int n_in,
                              void* d_out, int out_size)
{
    const float* xc   = (const float*)d_in[0];
    const float* yc   = (const float*)d_in[1];
    const float* mu   = (const float*)d_in[2];
    const float* istd = (const float*)d_in[3];
    const float* w1   = (const float*)d_in[4];
    const float* b1   = (const float*)d_in[5];
    const float* w2   = (const float*)d_in[6];
    const float* b2   = (const float*)d_in[7];
    const float* w3   = (const float*)d_in[8];
    const float* b3   = (const float*)d_in[9];
    const float* w4   = (const float*)d_in[10];
    const float* b4   = (const float*)d_in[11];
    const float* w5   = (const float*)d_in[12];
    const float* b5   = (const float*)d_in[13];
    float* out = (float*)d_out;

    dim3 g1(NTILE + 1, NCHv, NBv);   // 17 x 3 x 8 = 408 blocks
    k_all<<<g1, 512>>>(xc, yc, mu, istd, w1, b1,
                       w2, b2, w3, b3, w4, b4, w5, b5, out);
}